// round 9
// baseline (speedup 1.0000x reference)
#include <cuda_runtime.h>
#include <cuda_bf16.h>
#include <cuda_fp16.h>
#include <cstdint>

// ---------------------------------------------------------------- constants
#define H 128
#define BB 256
#define SS 1024
#define ROWS (BB*(SS-1))          // 261888
#define TM 128                    // rows per tile
#define NTILES (ROWS/TM)          // 2046 (exact)

#define YSTR 136                  // fp16 elems per y-tile row (padded)
#define ESTR 136                  // fp16 elems per e row (padded, bank-perfect)

// dynamic smem layout (bytes)
#define SM_Y    0                         // fp16 [128][136] = 34816
#define SM_DF   34816                     // B frags fp16, 32768
#define SM_E    (SM_DF + 32768)           // fp16 e=[x1-y], [128][136] = 34816
#define SMEM_TOTAL (SM_E + 34816)         // 102400 -> 2 CTAs/SM

// ---------------------------------------------------------------- scratch
__device__ float          g_B[H*H];          // C^2
__device__ __half         g_Dfrag[H*H];      // D fp16, mma B-fragment order
__device__ double         g_partials[NTILES];
__device__ double         g_l2row[H];        // per-row sum C^4
__device__ double         g_l2;              // sum C^4
__device__ unsigned int   g_done;            // main last-block counter
__device__ unsigned int   g_bar1;            // prep phase barrier
__device__ unsigned int   g_bar2;            // prep exit counter

// ---------------------------------------------------------------- helpers
__device__ __forceinline__ uint32_t smem_u32(const void* p) {
    uint32_t a;
    asm("{ .reg .u64 t; cvta.to.shared.u64 t, %1; cvt.u32.u64 %0, t; }"
        : "=r"(a) : "l"(p));
    return a;
}

#define MMA_F16(ACC, A0, A1, A2, A3, B0, B1)                                \
    asm volatile(                                                           \
        "mma.sync.aligned.m16n8k16.row.col.f32.f16.f16.f32 "                \
        "{%0,%1,%2,%3}, {%4,%5,%6,%7}, {%8,%9}, {%0,%1,%2,%3};"             \
        : "+f"((ACC)[0]), "+f"((ACC)[1]), "+f"((ACC)[2]), "+f"((ACC)[3])    \
        : "r"(A0), "r"(A1), "r"(A2), "r"(A3), "r"(B0), "r"(B1))

// ---------------------------------------------------------------- fused prep
// grid = 128 blocks x 512 threads, co-resident -> software global barrier.
// Block i owns row i; threads (j = t&127, kq = t>>7) split the k-dim 4-way.
__global__ void __launch_bounds__(512) prep_kernel(const float* __restrict__ coeff) {
    __shared__ float crow[H];
    __shared__ float brow[H];
    __shared__ float c2row[H];
    __shared__ float part[4][H];
    const int i  = blockIdx.x;
    const int t  = threadIdx.x;
    const int j  = t & 127;
    const int kq = t >> 7;          // 0..3

    if (t < H) crow[t] = coeff[i*H + t];
    __syncthreads();

    // ---- phase 1 partial: sum over k in [kq*32, kq*32+32) crow[k]*C[k][j]
    {
        float a0 = 0.f, a1 = 0.f;
        int k0 = kq * 32;
        #pragma unroll
        for (int k = 0; k < 32; k += 2) {
            a0 = fmaf(crow[k0+k],   __ldg(coeff + (k0+k)*H + j),   a0);
            a1 = fmaf(crow[k0+k+1], __ldg(coeff + (k0+k+1)*H + j), a1);
        }
        part[kq][j] = a0 + a1;
    }
    __syncthreads();
    if (t < H) {
        float b = (part[0][t] + part[1][t]) + (part[2][t] + part[3][t]);
        g_B[i*H + t] = b;
        brow[t]  = b;
        c2row[t] = crow[t] * (1.0f/6.0f) + b * (1.0f/24.0f);
        // per-row l2 partial
        float c = crow[t];
        float cc = c * c;
        float v = cc * cc;
        #pragma unroll
        for (int off = 16; off; off >>= 1)
            v += __shfl_down_sync(0xffffffffu, v, off);
        __shared__ float lred[4];
        if ((t & 31) == 0) lred[t >> 5] = v;
        __syncthreads();
        if (t == 0)
            g_l2row[i] = (double)((lred[0] + lred[1]) + (lred[2] + lred[3]));
    }

    // ---- global barrier (128 blocks, all resident)
    __threadfence();
    __syncthreads();
    if (t == 0) {
        atomicAdd(&g_bar1, 1u);
        while (*(volatile unsigned int*)&g_bar1 < (unsigned int)H) { }
    }
    __syncthreads();
    __threadfence();

    // ---- phase 2 partial: sum over k-quarter of c2row[k]*B[k][j]
    {
        float a0 = 0.f, a1 = 0.f;
        int k0 = kq * 32;
        #pragma unroll
        for (int k = 0; k < 32; k += 2) {
            a0 = fmaf(c2row[k0+k],   __ldg(g_B + (k0+k)*H + j),   a0);
            a1 = fmaf(c2row[k0+k+1], __ldg(g_B + (k0+k+1)*H + j), a1);
        }
        part[kq][j] = a0 + a1;
    }
    __syncthreads();
    if (t < H) {
        float d = crow[t] + 0.5f * brow[t]
                + ((part[0][t] + part[1][t]) + (part[2][t] + part[3][t]));
        int ks = t >> 4, kin = t & 15;
        int reg = kin >> 3;
        int lane = ((i & 7) << 2) + ((kin & 7) >> 1);
        int ntile = i >> 3;
        int fidx = ((((ks*16 + ntile)*32 + lane)*2 + reg) << 1) + (t & 1);
        g_Dfrag[fidx] = __float2half_rn(d);
    }
    if (i == 0 && t == 0) {
        double s = 0.0;
        #pragma unroll
        for (int r = 0; r < H; r++) s += g_l2row[r];
        g_l2 = s;
        g_done = 0u;
    }

    // ---- exit: last block resets barrier counters for next graph replay
    __threadfence();
    __syncthreads();
    if (t == 0) {
        unsigned int old = atomicAdd(&g_bar2, 1u);
        if (old == (unsigned int)(H - 1)) { g_bar1 = 0u; g_bar2 = 0u; }
    }
}

// ---------------------------------------------------------------- main
// 256 threads, 2 CTAs/SM. Warp w: rows [32*(w&3), +32), n-tiles [8*(w>>2), +8).
// Load phase: y->fp16 smem AND e = x1-y -> fp16 smem (coalesced fp32 reads).
// HMMA P = y@D; epilogue sum((P - e)^2) entirely from smem/registers.
__global__ void __launch_bounds__(256, 2)
main_kernel(const float* __restrict__ x, float* __restrict__ out) {
    extern __shared__ char smem[];
    const int tid  = threadIdx.x;
    const int tile = blockIdx.x;

    // ---- stage D B-fragments, 32KB
    {
        const uint4* df = (const uint4*)g_Dfrag;
        uint4* sh = (uint4*)(smem + SM_DF);
        #pragma unroll
        for (int i = 0; i < 8; i++) sh[tid + i*256] = df[tid + i*256];
    }

    // ---- load y + x1 (coalesced float4), write y fp16 + e=(x1-y) fp16
    {
        int row = tid >> 1, half = tid & 1;
        int rg = tile*TM + row;
        int b  = rg / 1023;
        int s  = rg - b*1023;
        const float4* src = (const float4*)(x + (size_t)(b*SS + s)*H) + half*16;
        char* ydst = smem + SM_Y + (size_t)row*YSTR*2 + half*128;
        char* edst = smem + SM_E + (size_t)row*ESTR*2 + half*128;
        #pragma unroll
        for (int q = 0; q < 8; q++) {
            float4 v0 = src[2*q], v1 = src[2*q + 1];
            float4 w0 = src[32 + 2*q], w1 = src[32 + 2*q + 1];   // x1 = row s+1
            __half2 p0 = __floats2half2_rn(v0.x, v0.y);
            __half2 p1 = __floats2half2_rn(v0.z, v0.w);
            __half2 p2 = __floats2half2_rn(v1.x, v1.y);
            __half2 p3 = __floats2half2_rn(v1.z, v1.w);
            uint4 u;
            u.x = *(uint32_t*)&p0; u.y = *(uint32_t*)&p1;
            u.z = *(uint32_t*)&p2; u.w = *(uint32_t*)&p3;
            *(uint4*)(ydst + q*16) = u;
            __half2 e0 = __floats2half2_rn(w0.x - v0.x, w0.y - v0.y);
            __half2 e1 = __floats2half2_rn(w0.z - v0.z, w0.w - v0.w);
            __half2 e2 = __floats2half2_rn(w1.x - v1.x, w1.y - v1.y);
            __half2 e3 = __floats2half2_rn(w1.z - v1.z, w1.w - v1.w);
            uint4 ue;
            ue.x = *(uint32_t*)&e0; ue.y = *(uint32_t*)&e1;
            ue.z = *(uint32_t*)&e2; ue.w = *(uint32_t*)&e3;
            *(uint4*)(edst + q*16) = ue;
        }
    }
    __syncthreads();

    // ---- HMMA mainloop (B frags hoisted: loaded once, used for both rt)
    const int w    = tid >> 5;
    const int lane = tid & 31;
    const int rb   = (w & 3) * 32;       // row base (2 m16 tiles)
    const int cb   = (w >> 2) * 8;       // n-tile base (8 tiles = 64 cols)

    float acc[2][8][4];
    #pragma unroll
    for (int rt = 0; rt < 2; rt++)
        #pragma unroll
        for (int t = 0; t < 8; t++) {
            acc[rt][t][0] = 0.f; acc[rt][t][1] = 0.f;
            acc[rt][t][2] = 0.f; acc[rt][t][3] = 0.f;
        }

    const uint32_t sY = smem_u32(smem) + SM_Y;
    const uint32_t abase = sY + (uint32_t)((rb + (lane & 15))*YSTR + (lane >> 4)*8)*2;

    #pragma unroll
    for (int ks = 0; ks < 8; ks++) {
        uint2 bf[8];
        #pragma unroll
        for (int t = 0; t < 8; t++) {
            uint32_t foff = (uint32_t)(((ks*16 + cb + t)*32 + lane) * 8);
            bf[t] = *(const uint2*)(smem + SM_DF + foff);
        }
        #pragma unroll
        for (int rt = 0; rt < 2; rt++) {
            uint32_t a0, a1, a2, a3;
            asm volatile("ldmatrix.sync.aligned.m8n8.x4.shared.b16 {%0,%1,%2,%3}, [%4];"
                         : "=r"(a0), "=r"(a1), "=r"(a2), "=r"(a3)
                         : "r"(abase + (uint32_t)(rt*16*YSTR*2) + ks*32));
            #pragma unroll
            for (int t = 0; t < 8; t++)
                MMA_F16(acc[rt][t], a0, a1, a2, a3, bf[t].x, bf[t].y);
        }
    }

    // ---- epilogue: d = P - e, all from smem (bank-conflict-free LDS.32)
    float lsum = 0.f;
    const char* E = smem + SM_E;
    #pragma unroll
    for (int rt = 0; rt < 2; rt++) {
        #pragma unroll
        for (int rr = 0; rr < 2; rr++) {
            int r = rb + rt*16 + rr*8 + (lane >> 2);
            const char* erow = E + (size_t)r*ESTR*2 + (lane & 3)*4;
            #pragma unroll
            for (int t = 0; t < 8; t++) {
                __half2 eh = *(const __half2*)(erow + (cb + t)*16);
                float2 ef = __half22float2(eh);
                float d;
                d = acc[rt][t][rr*2+0] - ef.x; lsum = fmaf(d, d, lsum);
                d = acc[rt][t][rr*2+1] - ef.y; lsum = fmaf(d, d, lsum);
            }
        }
    }

    // ---- CTA reduction
    #pragma unroll
    for (int off = 16; off; off >>= 1)
        lsum += __shfl_down_sync(0xffffffffu, lsum, off);
    __shared__ float red[8];
    if (lane == 0) red[w] = lsum;
    __syncthreads();

    __shared__ bool is_last;
    if (tid == 0) {
        float s = 0.f;
        #pragma unroll
        for (int i = 0; i < 8; i++) s += red[i];
        g_partials[tile] = (double)s;
        __threadfence();
        unsigned int old = atomicAdd(&g_done, 1u);
        is_last = (old == (unsigned int)(NTILES - 1));
    }
    __syncthreads();

    // ---- last CTA folds the global sum (fixed order -> deterministic)
    if (is_last) {
        double s = 0.0;
        for (int i = tid; i < NTILES; i += 256) s += g_partials[i];
        __shared__ double sd[256];
        sd[tid] = s; __syncthreads();
        for (int off = 128; off; off >>= 1) {
            if (tid < off) sd[tid] += sd[tid + off];
            __syncthreads();
        }
        if (tid == 0) {
            double step_loss = sd[0] / ((double)ROWS * (double)H);
            double l2_loss   = g_l2 / ((double)H * (double)H);
            out[0] = (float)(step_loss + 0.001 * l2_loss);
        }
    }
}

// ---------------------------------------------------------------- launch
extern "C" void kernel_launch(void* const* d_in, const int* in_sizes, int n_in,
                              void* d_out, int out_size) {
    const float* x     = (const float*)d_in[0];
    const float* coeff = (const float*)d_in[1];
    if (n_in >= 2 && in_sizes[0] == H*H) {
        coeff = (const float*)d_in[0];
        x     = (const float*)d_in[1];
    }
    float* out = (float*)d_out;

    cudaFuncSetAttribute(main_kernel,
                         cudaFuncAttributeMaxDynamicSharedMemorySize, SMEM_TOTAL);

    prep_kernel<<<H, 512>>>(coeff);
    main_kernel<<<NTILES, 256, SMEM_TOTAL>>>(x, out);
}

// round 10
// speedup vs baseline: 1.1791x; 1.1791x over previous
#include <cuda_runtime.h>
#include <cuda_bf16.h>
#include <cuda_fp16.h>
#include <cstdint>

// ---------------------------------------------------------------- constants
#define H 128
#define BB 256
#define SS 1024
#define ROWS (BB*(SS-1))          // 261888
#define TM 128                    // rows per tile
#define NTILES (ROWS/TM)          // 2046 (exact)
#define NCTA 296                  // persistent CTAs (2 per SM x 148)

#define YSTR 136                  // fp16 elems per y-tile row (padded)

// dynamic smem layout (bytes)
#define SM_DF   0                         // B frags fp16, 32768
#define SM_Y0   32768                     // fp16 y buf0 [128][136] = 34816
#define SM_Y1   (SM_Y0 + 34816)           // fp16 y buf1
#define SMEM_TOTAL (SM_Y1 + 34816)        // 102400 -> 2 CTAs/SM

// ---------------------------------------------------------------- scratch
__device__ float          g_B[H*H];          // C^2
__device__ __half         g_Dfrag[H*H];      // D fp16, mma B-fragment order
__device__ double         g_partials[NCTA];
__device__ double         g_l2row[H];        // per-row sum C^4
__device__ double         g_l2;              // sum C^4
__device__ unsigned int   g_done;            // main last-block counter
__device__ unsigned int   g_bar1;            // prep phase barrier
__device__ unsigned int   g_bar2;            // prep exit counter

// ---------------------------------------------------------------- helpers
__device__ __forceinline__ uint32_t smem_u32(const void* p) {
    uint32_t a;
    asm("{ .reg .u64 t; cvta.to.shared.u64 t, %1; cvt.u32.u64 %0, t; }"
        : "=r"(a) : "l"(p));
    return a;
}

#define MMA_F16(ACC, A0, A1, A2, A3, B0, B1)                                \
    asm volatile(                                                           \
        "mma.sync.aligned.m16n8k16.row.col.f32.f16.f16.f32 "                \
        "{%0,%1,%2,%3}, {%4,%5,%6,%7}, {%8,%9}, {%0,%1,%2,%3};"             \
        : "+f"((ACC)[0]), "+f"((ACC)[1]), "+f"((ACC)[2]), "+f"((ACC)[3])    \
        : "r"(A0), "r"(A1), "r"(A2), "r"(A3), "r"(B0), "r"(B1))

// ---------------------------------------------------------------- fused prep
// grid = 128 blocks x 512 threads, co-resident -> software global barrier.
__global__ void __launch_bounds__(512) prep_kernel(const float* __restrict__ coeff) {
    __shared__ float crow[H];
    __shared__ float brow[H];
    __shared__ float c2row[H];
    __shared__ float part[4][H];
    const int i  = blockIdx.x;
    const int t  = threadIdx.x;
    const int j  = t & 127;
    const int kq = t >> 7;          // 0..3

    if (t < H) crow[t] = coeff[i*H + t];
    __syncthreads();

    // ---- phase 1 partial: sum over k-quarter of crow[k]*C[k][j]
    {
        float a0 = 0.f, a1 = 0.f;
        int k0 = kq * 32;
        #pragma unroll
        for (int k = 0; k < 32; k += 2) {
            a0 = fmaf(crow[k0+k],   __ldg(coeff + (k0+k)*H + j),   a0);
            a1 = fmaf(crow[k0+k+1], __ldg(coeff + (k0+k+1)*H + j), a1);
        }
        part[kq][j] = a0 + a1;
    }
    __syncthreads();
    if (t < H) {
        float b = (part[0][t] + part[1][t]) + (part[2][t] + part[3][t]);
        g_B[i*H + t] = b;
        brow[t]  = b;
        c2row[t] = crow[t] * (1.0f/6.0f) + b * (1.0f/24.0f);
        float c = crow[t];
        float cc = c * c;
        float v = cc * cc;
        #pragma unroll
        for (int off = 16; off; off >>= 1)
            v += __shfl_down_sync(0xffffffffu, v, off);
        __shared__ float lred[4];
        if ((t & 31) == 0) lred[t >> 5] = v;
        __syncthreads();
        if (t == 0)
            g_l2row[i] = (double)((lred[0] + lred[1]) + (lred[2] + lred[3]));
    }

    // ---- global barrier (128 blocks, all resident)
    __threadfence();
    __syncthreads();
    if (t == 0) {
        atomicAdd(&g_bar1, 1u);
        while (*(volatile unsigned int*)&g_bar1 < (unsigned int)H) { }
    }
    __syncthreads();
    __threadfence();

    // ---- phase 2 partial: sum over k-quarter of c2row[k]*B[k][j]
    {
        float a0 = 0.f, a1 = 0.f;
        int k0 = kq * 32;
        #pragma unroll
        for (int k = 0; k < 32; k += 2) {
            a0 = fmaf(c2row[k0+k],   __ldg(g_B + (k0+k)*H + j),   a0);
            a1 = fmaf(c2row[k0+k+1], __ldg(g_B + (k0+k+1)*H + j), a1);
        }
        part[kq][j] = a0 + a1;
    }
    __syncthreads();
    if (t < H) {
        float d = crow[t] + 0.5f * brow[t]
                + ((part[0][t] + part[1][t]) + (part[2][t] + part[3][t]));
        int ks = t >> 4, kin = t & 15;
        int reg = kin >> 3;
        int lane = ((i & 7) << 2) + ((kin & 7) >> 1);
        int ntile = i >> 3;
        int fidx = ((((ks*16 + ntile)*32 + lane)*2 + reg) << 1) + (t & 1);
        g_Dfrag[fidx] = __float2half_rn(d);
    }
    if (i == 0 && t == 0) {
        double s = 0.0;
        #pragma unroll
        for (int r = 0; r < H; r++) s += g_l2row[r];
        g_l2 = s;
        g_done = 0u;
    }

    __threadfence();
    __syncthreads();
    if (t == 0) {
        unsigned int old = atomicAdd(&g_bar2, 1u);
        if (old == (unsigned int)(H - 1)) { g_bar1 = 0u; g_bar2 = 0u; }
    }
}

// ---------------------------------------------------------------- convert
// load fp32 y rows of tile tt (coalesced float4) -> fp16 smem buffer
__device__ __forceinline__ void convert_tile(const float* __restrict__ x,
                                             char* __restrict__ ybuf,
                                             int tt, int tid) {
    int row = tid >> 1, half = tid & 1;
    int rg = tt*TM + row;
    int b  = rg / 1023;
    int s  = rg - b*1023;
    const float4* src = (const float4*)(x + (size_t)(b*SS + s)*H) + half*16;
    char* dst = ybuf + (size_t)row*YSTR*2 + half*128;
    #pragma unroll
    for (int q = 0; q < 8; q++) {
        float4 v0 = src[2*q], v1 = src[2*q + 1];
        __half2 p0 = __floats2half2_rn(v0.x, v0.y);
        __half2 p1 = __floats2half2_rn(v0.z, v0.w);
        __half2 p2 = __floats2half2_rn(v1.x, v1.y);
        __half2 p3 = __floats2half2_rn(v1.z, v1.w);
        uint4 u;
        u.x = *(uint32_t*)&p0; u.y = *(uint32_t*)&p1;
        u.z = *(uint32_t*)&p2; u.w = *(uint32_t*)&p3;
        *(uint4*)(dst + q*16) = u;
    }
}

// ---------------------------------------------------------------- main
// Persistent: 296 CTAs x 256 threads, 2 CTAs/SM. D staged once per CTA.
// Double-buffered y tiles; epilogue: y from fp16 smem, x1 from global.
__global__ void __launch_bounds__(256, 2)
main_kernel(const float* __restrict__ x, float* __restrict__ out) {
    extern __shared__ char smem[];
    const int tid  = threadIdx.x;
    const int w    = tid >> 5;
    const int lane = tid & 31;
    const int rb   = (w & 3) * 32;       // row base (2 m16 tiles)
    const int cb   = (w >> 2) * 8;       // n-tile base (8 tiles = 64 cols)

    // ---- stage D B-fragments once, 32KB
    {
        const uint4* df = (const uint4*)g_Dfrag;
        uint4* sh = (uint4*)(smem + SM_DF);
        #pragma unroll
        for (int i = 0; i < 8; i++) sh[tid + i*256] = df[tid + i*256];
    }

    // ---- first tile convert
    int buf = 0;
    convert_tile(x, smem + SM_Y0, blockIdx.x, tid);
    __syncthreads();

    double csum = 0.0;                    // tid 0 accumulates per-CTA sum

    for (int tile = blockIdx.x; tile < NTILES; tile += NCTA) {
        char* ycur = smem + (buf ? SM_Y1 : SM_Y0);
        char* ynxt = smem + (buf ? SM_Y0 : SM_Y1);

        // ---- HMMA mainloop from ycur
        float acc[2][8][4];
        #pragma unroll
        for (int rt = 0; rt < 2; rt++)
            #pragma unroll
            for (int t = 0; t < 8; t++) {
                acc[rt][t][0] = 0.f; acc[rt][t][1] = 0.f;
                acc[rt][t][2] = 0.f; acc[rt][t][3] = 0.f;
            }
        const uint32_t abase = smem_u32(ycur)
            + (uint32_t)((rb + (lane & 15))*YSTR + (lane >> 4)*8)*2;

        #pragma unroll
        for (int ks = 0; ks < 8; ks++) {
            uint2 bf[8];
            #pragma unroll
            for (int t = 0; t < 8; t++) {
                uint32_t foff = (uint32_t)(((ks*16 + cb + t)*32 + lane) * 8);
                bf[t] = *(const uint2*)(smem + SM_DF + foff);
            }
            #pragma unroll
            for (int rt = 0; rt < 2; rt++) {
                uint32_t a0, a1, a2, a3;
                asm volatile("ldmatrix.sync.aligned.m8n8.x4.shared.b16 {%0,%1,%2,%3}, [%4];"
                             : "=r"(a0), "=r"(a1), "=r"(a2), "=r"(a3)
                             : "r"(abase + (uint32_t)(rt*16*YSTR*2) + ks*32));
                #pragma unroll
                for (int t = 0; t < 8; t++)
                    MMA_F16(acc[rt][t], a0, a1, a2, a3, bf[t].x, bf[t].y);
            }
        }

        // ---- prefetch/convert next tile into the other buffer
        int ntile = tile + NCTA;
        if (ntile < NTILES) convert_tile(x, ynxt, ntile, tid);

        // ---- epilogue: d = y(smem fp16) + P - x1(global fp32)
        float lsum = 0.f;
        #pragma unroll
        for (int rt = 0; rt < 2; rt++) {
            #pragma unroll
            for (int rr = 0; rr < 2; rr++) {
                int r = rb + rt*16 + rr*8 + (lane >> 2);
                int rg = tile*TM + r;
                int b  = rg / 1023;
                int s  = rg - b*1023;
                const float* x1b = x + (size_t)(b*SS + s + 1)*H;
                const char* yrow = ycur + (size_t)r*YSTR*2 + (lane & 3)*4;
                #pragma unroll
                for (int t = 0; t < 8; t++) {
                    int col = (cb + t)*8 + (lane & 3)*2;
                    float2 xv = *(const float2*)(x1b + col);
                    __half2 yh = *(const __half2*)(yrow + (cb + t)*16);
                    float2 yf = __half22float2(yh);
                    float d;
                    d = yf.x + acc[rt][t][rr*2+0] - xv.x; lsum = fmaf(d, d, lsum);
                    d = yf.y + acc[rt][t][rr*2+1] - xv.y; lsum = fmaf(d, d, lsum);
                }
            }
        }

        // ---- CTA reduction for this tile
        #pragma unroll
        for (int off = 16; off; off >>= 1)
            lsum += __shfl_down_sync(0xffffffffu, lsum, off);
        __shared__ float red[8];
        if (lane == 0) red[w] = lsum;
        __syncthreads();
        if (tid == 0) {
            float s = 0.f;
            #pragma unroll
            for (int i = 0; i < 8; i++) s += red[i];
            csum += (double)s;
        }
        __syncthreads();          // red reuse + ycur overwrite protection
        buf ^= 1;
    }

    // ---- publish per-CTA partial; last CTA folds (fixed order)
    __shared__ bool is_last;
    if (tid == 0) {
        g_partials[blockIdx.x] = csum;
        __threadfence();
        unsigned int old = atomicAdd(&g_done, 1u);
        is_last = (old == (unsigned int)(NCTA - 1));
    }
    __syncthreads();

    if (is_last) {
        double s = (tid < NCTA) ? g_partials[tid] : 0.0;
        if (tid + 256 < NCTA) s += g_partials[tid + 256];
        __shared__ double sd[256];
        sd[tid] = s; __syncthreads();
        for (int off = 128; off; off >>= 1) {
            if (tid < off) sd[tid] += sd[tid + off];
            __syncthreads();
        }
        if (tid == 0) {
            double step_loss = sd[0] / ((double)ROWS * (double)H);
            double l2_loss   = g_l2 / ((double)H * (double)H);
            out[0] = (float)(step_loss + 0.001 * l2_loss);
        }
    }
}

// ---------------------------------------------------------------- launch
extern "C" void kernel_launch(void* const* d_in, const int* in_sizes, int n_in,
                              void* d_out, int out_size) {
    const float* x     = (const float*)d_in[0];
    const float* coeff = (const float*)d_in[1];
    if (n_in >= 2 && in_sizes[0] == H*H) {
        coeff = (const float*)d_in[0];
        x     = (const float*)d_in[1];
    }
    float* out = (float*)d_out;

    cudaFuncSetAttribute(main_kernel,
                         cudaFuncAttributeMaxDynamicSharedMemorySize, SMEM_TOTAL);

    prep_kernel<<<H, 512>>>(coeff);
    main_kernel<<<NCTA, 256, SMEM_TOTAL>>>(x, out);
}